// round 1
// baseline (speedup 1.0000x reference)
#include <cuda_runtime.h>
#include <cuda_bf16.h>
#include <math.h>

// Problem constants (fixed by the reference setup)
#define BATCH 2
#define SEQ   2048
#define ROWS  (BATCH * SEQ)   // 4096
#define CDIM  256             // CQ == CC
#define DHALF 50
#define KWIN  101             // 2*D+1
#define PSIZE 100

// Scratch (allocation-free rule: __device__ globals)
__device__ float g_u[ROWS * CDIM];   // u = c_t @ W_a   [4096,256]
__device__ float g_p[ROWS];          // predicted centers

// ---------------------------------------------------------------------------
// Kernel 1: p = S * sigmoid( tanh(c_t @ W_p^T) @ V_p^T )
// Persistent blocks so W_p (100*256*4 = 102 KB) stays L1-resident per SM.
// ---------------------------------------------------------------------------
__global__ void __launch_bounds__(256) p_kernel(
    const float* __restrict__ c_t,
    const float* __restrict__ W_p,
    const float* __restrict__ V_p,
    float* __restrict__ p_out)
{
    __shared__ float sc[CDIM];
    __shared__ float wacc[8];
    const int tid  = threadIdx.x;
    const int warp = tid >> 5;
    const int lane = tid & 31;

    for (int r = blockIdx.x; r < ROWS; r += gridDim.x) {
        __syncthreads();                       // protect sc/wacc reuse
        sc[tid] = c_t[r * CDIM + tid];
        __syncthreads();

        float acc = 0.f;
        for (int j = warp; j < PSIZE; j += 8) {
            const float* wr = W_p + j * CDIM;
            float s = 0.f;
            #pragma unroll
            for (int c = lane; c < CDIM; c += 32)
                s += __ldg(wr + c) * sc[c];
            #pragma unroll
            for (int o = 16; o; o >>= 1)
                s += __shfl_xor_sync(0xffffffffu, s, o);
            if (lane == 0)
                acc += __ldg(V_p + j) * tanhf(s);
        }
        if (lane == 0) wacc[warp] = acc;
        __syncthreads();
        if (tid == 0) {
            float t = 0.f;
            #pragma unroll
            for (int w = 0; w < 8; w++) t += wacc[w];
            p_out[r] = (float)SEQ / (1.f + expf(-t));
        }
    }
}

// ---------------------------------------------------------------------------
// Kernel 2: u[r, n] = sum_c c_t[r, c] * W_a[c, n]
// M=4096, K=256, N=256. 64x64x32 tiles, 4x4 microtiles, 256 threads.
// ---------------------------------------------------------------------------
__global__ void __launch_bounds__(256) gemm_u_kernel(
    const float* __restrict__ A,    // c_t [4096,256]
    const float* __restrict__ Bm,   // W_a [256,256]
    float* __restrict__ C)          // u   [4096,256]
{
    const int BM = 64, BN = 64, BK = 32;
    __shared__ float As[32][64 + 4];   // transposed A tile, padded
    __shared__ float Bs[32][64];

    const int tid = threadIdx.x;
    const int rowBase = blockIdx.y * BM;
    const int colBase = blockIdx.x * BN;
    const int tx = tid & 15;   // n microtile
    const int ty = tid >> 4;   // m microtile

    float acc[4][4] = {};

    for (int k0 = 0; k0 < CDIM; k0 += BK) {
        // load A tile 64x32 (512 float4), store transposed As[k][m]
        #pragma unroll
        for (int t = 0; t < 2; t++) {
            int i  = tid + t * 256;
            int r  = i >> 3;        // 8 float4 per row
            int c4 = i & 7;
            float4 v = *(const float4*)&A[(rowBase + r) * CDIM + k0 + c4 * 4];
            As[c4 * 4 + 0][r] = v.x;
            As[c4 * 4 + 1][r] = v.y;
            As[c4 * 4 + 2][r] = v.z;
            As[c4 * 4 + 3][r] = v.w;
        }
        // load B tile 32x64 (512 float4)
        #pragma unroll
        for (int t = 0; t < 2; t++) {
            int i  = tid + t * 256;
            int r  = i >> 4;        // 16 float4 per row
            int c4 = i & 15;
            *(float4*)&Bs[r][c4 * 4] =
                *(const float4*)&Bm[(k0 + r) * CDIM + colBase + c4 * 4];
        }
        __syncthreads();

        #pragma unroll
        for (int kk = 0; kk < BK; kk++) {
            float a0 = As[kk][ty * 4 + 0];
            float a1 = As[kk][ty * 4 + 1];
            float a2 = As[kk][ty * 4 + 2];
            float a3 = As[kk][ty * 4 + 3];
            float4 b = *(float4*)&Bs[kk][tx * 4];
            acc[0][0] += a0 * b.x; acc[0][1] += a0 * b.y; acc[0][2] += a0 * b.z; acc[0][3] += a0 * b.w;
            acc[1][0] += a1 * b.x; acc[1][1] += a1 * b.y; acc[1][2] += a1 * b.z; acc[1][3] += a1 * b.w;
            acc[2][0] += a2 * b.x; acc[2][1] += a2 * b.y; acc[2][2] += a2 * b.z; acc[2][3] += a2 * b.w;
            acc[3][0] += a3 * b.x; acc[3][1] += a3 * b.y; acc[3][2] += a3 * b.z; acc[3][3] += a3 * b.w;
        }
        __syncthreads();
    }

    #pragma unroll
    for (int i = 0; i < 4; i++) {
        float4 v = make_float4(acc[i][0], acc[i][1], acc[i][2], acc[i][3]);
        *(float4*)&C[(rowBase + ty * 4 + i) * CDIM + colBase + tx * 4] = v;
    }
}

// ---------------------------------------------------------------------------
// Kernel 3: gather window -> smem, scores, softmax * gaussian, weighted sum.
// One block (256 threads) per (b, s) row. Window staged once in shared memory
// so both the score dots and the output sum read smem (halves L2 traffic).
// ---------------------------------------------------------------------------
#define KPAD 104
#define ATTN_SMEM_FLOATS (KWIN * CDIM + CDIM + KPAD)  // win + u + a/w
#define ATTN_SMEM_BYTES  (ATTN_SMEM_FLOATS * 4 + KPAD * 4)  // + int idx

__global__ void __launch_bounds__(256) attn_kernel(
    const float* __restrict__ q,     // [B, S, C]
    const float* __restrict__ u,     // [ROWS, C]
    const float* __restrict__ p,     // [ROWS]
    float* __restrict__ out)         // [ROWS, C]
{
    extern __shared__ float smem[];
    float* win  = smem;                        // [KWIN][CDIM]
    float* su   = win + KWIN * CDIM;           // [CDIM]
    float* sa   = su + CDIM;                   // [KPAD] scores -> weights
    int*   sidx = (int*)(sa + KPAD);           // [KPAD]

    const int r    = blockIdx.x;               // 0..4095
    const int b    = r / SEQ;
    const int tid  = threadIdx.x;
    const int warp = tid >> 5;
    const int lane = tid & 31;

    const float pv = p[r];

    su[tid] = u[r * CDIM + tid];
    if (tid < KWIN) {
        int off   = tid - DHALF;
        float raw = truncf(pv + (float)off + 1.0f);
        int ri = (int)raw;
        ri = min(max(ri, 0), SEQ + 1);
        if (ri == SEQ + 1) ri = 0;             // % (S+1)
        sidx[tid] = ri;                        // 0 == invalid
    }
    __syncthreads();

    // ---- stage window into smem (float4, L2-resident gather) ----
    {
        const float4* qb = (const float4*)(q + (size_t)b * SEQ * CDIM);
        float4* winv = (float4*)win;
        #pragma unroll 4
        for (int i = tid; i < KWIN * (CDIM / 4); i += 256) {
            int k = i >> 6;                    // / 64
            int j = i & 63;
            int ri = sidx[k];
            float4 v = make_float4(0.f, 0.f, 0.f, 0.f);
            if (ri != 0) v = qb[(size_t)(ri - 1) * (CDIM / 4) + j];
            winv[(size_t)k * (CDIM / 4) + j] = v;
        }
    }
    __syncthreads();

    // ---- scores: a[k] = win[k,:] . u ----
    for (int k = warp; k < KWIN; k += 8) {
        const float* wr = win + k * CDIM;
        float s = 0.f;
        #pragma unroll
        for (int c = lane; c < CDIM; c += 32)
            s += wr[c] * su[c];
        #pragma unroll
        for (int o = 16; o; o >>= 1)
            s += __shfl_xor_sync(0xffffffffu, s, o);
        if (lane == 0)
            sa[k] = (sidx[k] == 0) ? -INFINITY : s;
    }
    __syncthreads();

    // ---- softmax over k + gaussian decay (warp 0) ----
    if (tid < 32) {
        float v[4];
        float m = -INFINITY;
        #pragma unroll
        for (int t = 0; t < 4; t++) {
            int k = tid + t * 32;
            v[t] = (k < KWIN) ? sa[k] : -INFINITY;
            m = fmaxf(m, v[t]);
        }
        #pragma unroll
        for (int o = 16; o; o >>= 1)
            m = fmaxf(m, __shfl_xor_sync(0xffffffffu, m, o));
        float ssum = 0.f;
        #pragma unroll
        for (int t = 0; t < 4; t++) {
            int k = tid + t * 32;
            float e = (k < KWIN) ? expf(v[t] - m) : 0.f;
            v[t] = e;
            ssum += e;
        }
        #pragma unroll
        for (int o = 16; o; o >>= 1)
            ssum += __shfl_xor_sync(0xffffffffu, ssum, o);
        float inv = 1.f / ssum;
        float fp  = truncf(pv);
        #pragma unroll
        for (int t = 0; t < 4; t++) {
            int k = tid + t * 32;
            if (k < KWIN) {
                float d = ((float)(k - DHALF) + fp - pv) / (float)DHALF;
                sa[k] = v[t] * inv * expf(-2.f * d * d);
            }
        }
    }
    __syncthreads();

    // ---- output: s_t[c] = sum_k w[k] * win[k][c] ----
    float acc = 0.f;
    #pragma unroll 4
    for (int k = 0; k < KWIN; k++)
        acc += sa[k] * win[k * CDIM + tid];
    out[r * CDIM + tid] = acc;
}

// ---------------------------------------------------------------------------
extern "C" void kernel_launch(void* const* d_in, const int* in_sizes, int n_in,
                              void* d_out, int out_size)
{
    const float* q   = (const float*)d_in[0];
    const float* c_t = (const float*)d_in[1];
    const float* W_a = (const float*)d_in[2];
    const float* W_p = (const float*)d_in[3];
    const float* V_p = (const float*)d_in[4];
    float* out = (float*)d_out;

    float* u = nullptr;
    float* p = nullptr;
    cudaGetSymbolAddress((void**)&u, g_u);
    cudaGetSymbolAddress((void**)&p, g_p);

    static_assert(ATTN_SMEM_BYTES < 110 * 1024, "smem budget");
    cudaFuncSetAttribute(attn_kernel, cudaFuncAttributeMaxDynamicSharedMemorySize,
                         ATTN_SMEM_BYTES);

    p_kernel<<<296, 256>>>(c_t, W_p, V_p, p);
    gemm_u_kernel<<<dim3(CDIM / 64, ROWS / 64), 256>>>(c_t, W_a, u);
    attn_kernel<<<ROWS, 256, ATTN_SMEM_BYTES>>>(q, u, p, out);
}

// round 5
// speedup vs baseline: 1.4143x; 1.4143x over previous
#include <cuda_runtime.h>
#include <cuda_bf16.h>
#include <math.h>

// Problem constants (fixed by the reference setup)
#define BATCH 2
#define SEQ   2048
#define ROWS  (BATCH * SEQ)   // 4096
#define CDIM  256             // CQ == CC
#define DHALF 50
#define KWIN  101             // 2*D+1
#define PSIZE 100
#define JPAD  128             // PSIZE padded

// Scratch (allocation-free rule: __device__ globals)
__device__ float g_u[ROWS * CDIM];   // u = c_t @ W_a   [4096,256]
__device__ float g_p[ROWS];          // predicted centers

// ---------------------------------------------------------------------------
// Combined projection kernel, 320 blocks:
//   blocks [0,256):   u[r,n] = sum_c c_t[r,c] * W_a[c,n]      (64x64 tiles)
//   blocks [256,320): p[r]   = S*sigmoid(sum_j V_p[j]*tanh(sum_c c_t[r,c]*W_p[j,c]))
// Both register-tiled GEMMs share one launch so they overlap on-chip.
// ---------------------------------------------------------------------------
__global__ void __launch_bounds__(256) proj_kernel(
    const float* __restrict__ A,     // c_t [4096,256]
    const float* __restrict__ W_a,   // [256,256]
    const float* __restrict__ W_p,   // [100,256]
    const float* __restrict__ V_p,   // [100]
    float* __restrict__ U,           // u [4096,256]
    float* __restrict__ P)           // p [4096]
{
    __shared__ float As[32][68];     // transposed A tile (k, m), padded
    __shared__ float Bs[32][132];    // (k, n/j) tile
    __shared__ float red[64][17];    // p-branch row reduction

    const int tid = threadIdx.x;
    const int bid = blockIdx.x;

    if (bid < 256) {
        // ---------------- u GEMM: 64x64x32 tiles, 4x4 microtile ----------------
        const int rowBase = (bid >> 2) * 64;
        const int colBase = (bid & 3) * 64;
        const int tx = tid & 15;
        const int ty = tid >> 4;

        float acc[4][4] = {};

        for (int k0 = 0; k0 < CDIM; k0 += 32) {
            #pragma unroll
            for (int t = 0; t < 2; t++) {
                int i  = tid + t * 256;
                int r  = i >> 3;
                int c4 = i & 7;
                float4 v = *(const float4*)&A[(rowBase + r) * CDIM + k0 + c4 * 4];
                As[c4 * 4 + 0][r] = v.x;
                As[c4 * 4 + 1][r] = v.y;
                As[c4 * 4 + 2][r] = v.z;
                As[c4 * 4 + 3][r] = v.w;
            }
            #pragma unroll
            for (int t = 0; t < 2; t++) {
                int i  = tid + t * 256;
                int r  = i >> 4;
                int c4 = i & 15;
                *(float4*)&Bs[r][c4 * 4] =
                    *(const float4*)&W_a[(k0 + r) * CDIM + colBase + c4 * 4];
            }
            __syncthreads();

            #pragma unroll
            for (int kk = 0; kk < 32; kk++) {
                float a0 = As[kk][ty * 4 + 0];
                float a1 = As[kk][ty * 4 + 1];
                float a2 = As[kk][ty * 4 + 2];
                float a3 = As[kk][ty * 4 + 3];
                float4 b = *(float4*)&Bs[kk][tx * 4];
                acc[0][0] += a0 * b.x; acc[0][1] += a0 * b.y; acc[0][2] += a0 * b.z; acc[0][3] += a0 * b.w;
                acc[1][0] += a1 * b.x; acc[1][1] += a1 * b.y; acc[1][2] += a1 * b.z; acc[1][3] += a1 * b.w;
                acc[2][0] += a2 * b.x; acc[2][1] += a2 * b.y; acc[2][2] += a2 * b.z; acc[2][3] += a2 * b.w;
                acc[3][0] += a3 * b.x; acc[3][1] += a3 * b.y; acc[3][2] += a3 * b.z; acc[3][3] += a3 * b.w;
            }
            __syncthreads();
        }

        #pragma unroll
        for (int i = 0; i < 4; i++) {
            float4 v = make_float4(acc[i][0], acc[i][1], acc[i][2], acc[i][3]);
            *(float4*)&U[(rowBase + ty * 4 + i) * CDIM + colBase + tx * 4] = v;
        }
    } else {
        // ---------------- p GEMM: 64 rows x 128(padded j) x 256 ----------------
        const int rowBase = (bid - 256) * 64;
        const int tx = tid & 15;    // j-tile: j = tx*8 .. tx*8+7
        const int ty = tid >> 4;    // rows  : ty*4 .. ty*4+3

        float vp[8];
        #pragma unroll
        for (int jj = 0; jj < 8; jj++) {
            int j = tx * 8 + jj;
            vp[jj] = (j < PSIZE) ? __ldg(V_p + j) : 0.f;
        }

        // zero Bs columns [100,128) once (never overwritten)
        for (int i = tid; i < 32 * (JPAD - PSIZE); i += 256) {
            int k = i / (JPAD - PSIZE);
            int j = PSIZE + i % (JPAD - PSIZE);
            Bs[k][j] = 0.f;
        }

        float acc[4][8] = {};

        for (int k0 = 0; k0 < CDIM; k0 += 32) {
            #pragma unroll
            for (int t = 0; t < 2; t++) {
                int i  = tid + t * 256;
                int r  = i >> 3;
                int c4 = i & 7;
                float4 v = *(const float4*)&A[(rowBase + r) * CDIM + k0 + c4 * 4];
                As[c4 * 4 + 0][r] = v.x;
                As[c4 * 4 + 1][r] = v.y;
                As[c4 * 4 + 2][r] = v.z;
                As[c4 * 4 + 3][r] = v.w;
            }
            for (int i = tid; i < PSIZE * 8; i += 256) {
                int j  = i >> 3;
                int c4 = i & 7;
                float4 v = *(const float4*)&W_p[j * CDIM + k0 + c4 * 4];
                Bs[c4 * 4 + 0][j] = v.x;
                Bs[c4 * 4 + 1][j] = v.y;
                Bs[c4 * 4 + 2][j] = v.z;
                Bs[c4 * 4 + 3][j] = v.w;
            }
            __syncthreads();

            #pragma unroll
            for (int kk = 0; kk < 32; kk++) {
                float a0 = As[kk][ty * 4 + 0];
                float a1 = As[kk][ty * 4 + 1];
                float a2 = As[kk][ty * 4 + 2];
                float a3 = As[kk][ty * 4 + 3];
                float4 b0 = *(float4*)&Bs[kk][tx * 8 + 0];
                float4 b1 = *(float4*)&Bs[kk][tx * 8 + 4];
                acc[0][0] += a0 * b0.x; acc[0][1] += a0 * b0.y; acc[0][2] += a0 * b0.z; acc[0][3] += a0 * b0.w;
                acc[0][4] += a0 * b1.x; acc[0][5] += a0 * b1.y; acc[0][6] += a0 * b1.z; acc[0][7] += a0 * b1.w;
                acc[1][0] += a1 * b0.x; acc[1][1] += a1 * b0.y; acc[1][2] += a1 * b0.z; acc[1][3] += a1 * b0.w;
                acc[1][4] += a1 * b1.x; acc[1][5] += a1 * b1.y; acc[1][6] += a1 * b1.z; acc[1][7] += a1 * b1.w;
                acc[2][0] += a2 * b0.x; acc[2][1] += a2 * b0.y; acc[2][2] += a2 * b0.z; acc[2][3] += a2 * b0.w;
                acc[2][4] += a2 * b1.x; acc[2][5] += a2 * b1.y; acc[2][6] += a2 * b1.z; acc[2][7] += a2 * b1.w;
                acc[3][0] += a3 * b0.x; acc[3][1] += a3 * b0.y; acc[3][2] += a3 * b0.z; acc[3][3] += a3 * b0.w;
                acc[3][4] += a3 * b1.x; acc[3][5] += a3 * b1.y; acc[3][6] += a3 * b1.z; acc[3][7] += a3 * b1.w;
            }
            __syncthreads();
        }

        #pragma unroll
        for (int i = 0; i < 4; i++) {
            float s = 0.f;
            #pragma unroll
            for (int jj = 0; jj < 8; jj++)
                s += vp[jj] * tanhf(acc[i][jj]);
            red[ty * 4 + i][tx] = s;
        }
        __syncthreads();
        if (tid < 64) {
            float s = 0.f;
            #pragma unroll
            for (int t = 0; t < 16; t++) s += red[tid][t];
            P[rowBase + tid] = (float)SEQ / (1.f + expf(-s));
        }
    }
}

// ---------------------------------------------------------------------------
// attn: FUSED gather+score (dot computed while window streams L2->smem),
// then softmax * gaussian, then weighted sum from smem.
// One block (256 threads) per (b, s) row.
// ---------------------------------------------------------------------------
#define KPAD 104
#define ATTN_SMEM_BYTES ((KWIN * CDIM + KPAD) * 4 + KPAD * 4)

__global__ void __launch_bounds__(256) attn_kernel(
    const float* __restrict__ q,     // [B, S, C]
    const float* __restrict__ u,     // [ROWS, C]
    const float* __restrict__ p,     // [ROWS]
    float* __restrict__ out)         // [ROWS, C]
{
    extern __shared__ float smem[];
    float* win  = smem;                        // [KWIN][CDIM]
    float* sa   = win + KWIN * CDIM;           // [KPAD] scores -> weights
    int*   sidx = (int*)(sa + KPAD);           // [KPAD]

    const int r    = blockIdx.x;
    const int b    = r / SEQ;
    const int tid  = threadIdx.x;
    const int warp = tid >> 5;
    const int lane = tid & 31;

    const float pv = p[r];

    if (tid < KWIN) {
        int off   = tid - DHALF;
        float raw = truncf(pv + (float)off + 1.0f);
        int ri = (int)raw;
        ri = min(max(ri, 0), SEQ + 1);
        if (ri == SEQ + 1) ri = 0;             // % (S+1); 0 == invalid
        sidx[tid] = ri;
    }
    // each lane caches its 2 u-float4s in registers (coalesced load)
    const float4* uv = (const float4*)(u + (size_t)r * CDIM);
    const float4 u0 = uv[lane];
    const float4 u1 = uv[lane + 32];
    __syncthreads();

    // ---- fused: gather window L2->smem AND score dot in one pass ----
    {
        const float4* qb = (const float4*)(q + (size_t)b * SEQ * CDIM);
        float4* winv = (float4*)win;
        #pragma unroll 2
        for (int k = warp; k < KWIN; k += 8) {
            const int ri = sidx[k];
            float4 a0 = make_float4(0.f, 0.f, 0.f, 0.f);
            float4 a1 = a0;
            if (ri != 0) {
                const float4* qr = qb + (size_t)(ri - 1) * (CDIM / 4);
                a0 = qr[lane];
                a1 = qr[lane + 32];
            }
            winv[(size_t)k * (CDIM / 4) + lane]      = a0;
            winv[(size_t)k * (CDIM / 4) + lane + 32] = a1;
            float s = a0.x * u0.x + a0.y * u0.y + a0.z * u0.z + a0.w * u0.w
                    + a1.x * u1.x + a1.y * u1.y + a1.z * u1.z + a1.w * u1.w;
            #pragma unroll
            for (int o = 16; o; o >>= 1)
                s += __shfl_xor_sync(0xffffffffu, s, o);
            if (lane == 0)
                sa[k] = (ri == 0) ? -INFINITY : s;
        }
    }
    __syncthreads();

    // ---- softmax over k + gaussian decay (warp 0) ----
    if (tid < 32) {
        float v[4];
        float m = -INFINITY;
        #pragma unroll
        for (int t = 0; t < 4; t++) {
            int k = tid + t * 32;
            v[t] = (k < KWIN) ? sa[k] : -INFINITY;
            m = fmaxf(m, v[t]);
        }
        #pragma unroll
        for (int o = 16; o; o >>= 1)
            m = fmaxf(m, __shfl_xor_sync(0xffffffffu, m, o));
        float ssum = 0.f;
        #pragma unroll
        for (int t = 0; t < 4; t++) {
            int k = tid + t * 32;
            float e = (k < KWIN) ? __expf(v[t] - m) : 0.f;
            v[t] = e;
            ssum += e;
        }
        #pragma unroll
        for (int o = 16; o; o >>= 1)
            ssum += __shfl_xor_sync(0xffffffffu, ssum, o);
        float inv = 1.f / ssum;
        float fp  = truncf(pv);
        #pragma unroll
        for (int t = 0; t < 4; t++) {
            int k = tid + t * 32;
            if (k < KWIN) {
                float d = ((float)(k - DHALF) + fp - pv) / (float)DHALF;
                sa[k] = v[t] * inv * __expf(-2.f * d * d);
            }
        }
    }
    __syncthreads();

    // ---- output: s_t[c] = sum_k w[k] * win[k][c] ----
    float acc = 0.f;
    #pragma unroll 4
    for (int k = 0; k < KWIN; k++)
        acc += sa[k] * win[k * CDIM + tid];
    out[r * CDIM + tid] = acc;
}

// ---------------------------------------------------------------------------
extern "C" void kernel_launch(void* const* d_in, const int* in_sizes, int n_in,
                              void* d_out, int out_size)
{
    const float* q   = (const float*)d_in[0];
    const float* c_t = (const float*)d_in[1];
    const float* W_a = (const float*)d_in[2];
    const float* W_p = (const float*)d_in[3];
    const float* V_p = (const float*)d_in[4];
    float* out = (float*)d_out;

    float* u = nullptr;
    float* p = nullptr;
    cudaGetSymbolAddress((void**)&u, g_u);
    cudaGetSymbolAddress((void**)&p, g_p);

    static_assert(ATTN_SMEM_BYTES < 110 * 1024, "smem budget");
    cudaFuncSetAttribute(attn_kernel, cudaFuncAttributeMaxDynamicSharedMemorySize,
                         ATTN_SMEM_BYTES);

    proj_kernel<<<320, 256>>>(c_t, W_a, W_p, V_p, u, p);
    attn_kernel<<<ROWS, 256, ATTN_SMEM_BYTES>>>(q, u, p, out);
}

// round 9
// speedup vs baseline: 1.6889x; 1.1941x over previous
#include <cuda_runtime.h>
#include <cuda_bf16.h>
#include <math.h>

// Problem constants (fixed by the reference setup)
#define BATCH 2
#define SEQ   2048
#define ROWS  (BATCH * SEQ)   // 4096
#define CDIM  256             // CQ == CC
#define DHALF 50
#define KWIN  101             // 2*D+1
#define PSIZE 100
#define JPAD  128             // PSIZE padded

// Scratch (allocation-free rule: __device__ globals)
__device__ float g_u[ROWS * CDIM];   // u = c_t @ W_a   [4096,256]
__device__ float g_p[ROWS];          // predicted centers

// ---------------------------------------------------------------------------
// Combined projection kernel, 192 blocks:
//   blocks [0,128):   u = c_t @ W_a   (128x64 tiles, BK=16, 8x4 microtile)
//   blocks [128,192): p = S*sigmoid(tanh(c_t@W_p^T)@V_p^T)   (64-row tiles)
// ---------------------------------------------------------------------------
#define PROJ_SBUF_FLOATS 7488   // max(u: 2240+1024, p: 2176+4224+1088)

__global__ void __launch_bounds__(256) proj_kernel(
    const float* __restrict__ A,     // c_t [4096,256]
    const float* __restrict__ W_a,   // [256,256]
    const float* __restrict__ W_p,   // [100,256]
    const float* __restrict__ V_p,   // [100]
    float* __restrict__ U,           // u [4096,256]
    float* __restrict__ P)           // p [4096]
{
    __shared__ __align__(16) float sbuf[PROJ_SBUF_FLOATS];

    const int tid = threadIdx.x;
    const int bid = blockIdx.x;

    if (bid < 128) {
        // ------- u GEMM: BM=128, BN=64, BK=16, 8x4 microtile -------
        float* As = sbuf;            // [16][140] transposed (k, m), 140 stride
        float* Bs = sbuf + 2240;     // [16][64]
        const int rowBase = (bid >> 2) * 128;
        const int colBase = (bid & 3) * 64;
        const int tx = tid & 15;     // n: 4 cols
        const int ty = tid >> 4;     // m: 8 rows

        float acc[8][4] = {};

        for (int k0 = 0; k0 < CDIM; k0 += 16) {
            // A tile 128x16 -> As[k][m] (512 float4)
            #pragma unroll
            for (int t = 0; t < 2; t++) {
                int i  = tid + t * 256;
                int r  = i >> 2;
                int c4 = i & 3;
                float4 v = *(const float4*)&A[(rowBase + r) * CDIM + k0 + c4 * 4];
                As[(c4 * 4 + 0) * 140 + r] = v.x;
                As[(c4 * 4 + 1) * 140 + r] = v.y;
                As[(c4 * 4 + 2) * 140 + r] = v.z;
                As[(c4 * 4 + 3) * 140 + r] = v.w;
            }
            // B tile 16x64 (256 float4)
            {
                int r  = tid >> 4;
                int c4 = tid & 15;
                *(float4*)&Bs[r * 64 + c4 * 4] =
                    *(const float4*)&W_a[(k0 + r) * CDIM + colBase + c4 * 4];
            }
            __syncthreads();

            #pragma unroll
            for (int kk = 0; kk < 16; kk++) {
                float4 A0 = *(float4*)&As[kk * 140 + ty * 8];
                float4 A1 = *(float4*)&As[kk * 140 + ty * 8 + 4];
                float4 Bv = *(float4*)&Bs[kk * 64 + tx * 4];
                float am[8] = {A0.x, A0.y, A0.z, A0.w, A1.x, A1.y, A1.z, A1.w};
                #pragma unroll
                for (int i = 0; i < 8; i++) {
                    acc[i][0] += am[i] * Bv.x;
                    acc[i][1] += am[i] * Bv.y;
                    acc[i][2] += am[i] * Bv.z;
                    acc[i][3] += am[i] * Bv.w;
                }
            }
            __syncthreads();
        }

        #pragma unroll
        for (int i = 0; i < 8; i++) {
            float4 v = make_float4(acc[i][0], acc[i][1], acc[i][2], acc[i][3]);
            *(float4*)&U[(rowBase + ty * 8 + i) * CDIM + colBase + tx * 4] = v;
        }
    } else {
        // ------- p GEMM: 64 rows x 128(padded j) x 256 (known-good) -------
        float* As  = sbuf;           // [32][68]
        float* Bs  = sbuf + 2176;    // [32][132]
        float* red = sbuf + 2176 + 4224;  // [64][17]
        const int rowBase = (bid - 128) * 64;
        const int tx = tid & 15;
        const int ty = tid >> 4;

        float vp[8];
        #pragma unroll
        for (int jj = 0; jj < 8; jj++) {
            int j = tx * 8 + jj;
            vp[jj] = (j < PSIZE) ? __ldg(V_p + j) : 0.f;
        }

        for (int i = tid; i < 32 * (JPAD - PSIZE); i += 256) {
            int k = i / (JPAD - PSIZE);
            int j = PSIZE + i % (JPAD - PSIZE);
            Bs[k * 132 + j] = 0.f;
        }

        float acc[4][8] = {};

        for (int k0 = 0; k0 < CDIM; k0 += 32) {
            #pragma unroll
            for (int t = 0; t < 2; t++) {
                int i  = tid + t * 256;
                int r  = i >> 3;
                int c4 = i & 7;
                float4 v = *(const float4*)&A[(rowBase + r) * CDIM + k0 + c4 * 4];
                As[(c4 * 4 + 0) * 68 + r] = v.x;
                As[(c4 * 4 + 1) * 68 + r] = v.y;
                As[(c4 * 4 + 2) * 68 + r] = v.z;
                As[(c4 * 4 + 3) * 68 + r] = v.w;
            }
            for (int i = tid; i < PSIZE * 8; i += 256) {
                int j  = i >> 3;
                int c4 = i & 7;
                float4 v = *(const float4*)&W_p[j * CDIM + k0 + c4 * 4];
                Bs[(c4 * 4 + 0) * 132 + j] = v.x;
                Bs[(c4 * 4 + 1) * 132 + j] = v.y;
                Bs[(c4 * 4 + 2) * 132 + j] = v.z;
                Bs[(c4 * 4 + 3) * 132 + j] = v.w;
            }
            __syncthreads();

            #pragma unroll
            for (int kk = 0; kk < 32; kk++) {
                float a0 = As[kk * 68 + ty * 4 + 0];
                float a1 = As[kk * 68 + ty * 4 + 1];
                float a2 = As[kk * 68 + ty * 4 + 2];
                float a3 = As[kk * 68 + ty * 4 + 3];
                float4 b0 = *(float4*)&Bs[kk * 132 + tx * 8 + 0];
                float4 b1 = *(float4*)&Bs[kk * 132 + tx * 8 + 4];
                acc[0][0] += a0 * b0.x; acc[0][1] += a0 * b0.y; acc[0][2] += a0 * b0.z; acc[0][3] += a0 * b0.w;
                acc[0][4] += a0 * b1.x; acc[0][5] += a0 * b1.y; acc[0][6] += a0 * b1.z; acc[0][7] += a0 * b1.w;
                acc[1][0] += a1 * b0.x; acc[1][1] += a1 * b0.y; acc[1][2] += a1 * b0.z; acc[1][3] += a1 * b0.w;
                acc[1][4] += a1 * b1.x; acc[1][5] += a1 * b1.y; acc[1][6] += a1 * b1.z; acc[1][7] += a1 * b1.w;
                acc[2][0] += a2 * b0.x; acc[2][1] += a2 * b0.y; acc[2][2] += a2 * b0.z; acc[2][3] += a2 * b0.w;
                acc[2][4] += a2 * b1.x; acc[2][5] += a2 * b1.y; acc[2][6] += a2 * b1.z; acc[2][7] += a2 * b1.w;
                acc[3][0] += a3 * b0.x; acc[3][1] += a3 * b0.y; acc[3][2] += a3 * b0.z; acc[3][3] += a3 * b0.w;
                acc[3][4] += a3 * b1.x; acc[3][5] += a3 * b1.y; acc[3][6] += a3 * b1.z; acc[3][7] += a3 * b1.w;
            }
            __syncthreads();
        }

        #pragma unroll
        for (int i = 0; i < 4; i++) {
            float s = 0.f;
            #pragma unroll
            for (int jj = 0; jj < 8; jj++)
                s += vp[jj] * tanhf(acc[i][jj]);
            red[(ty * 4 + i) * 17 + tx] = s;
        }
        __syncthreads();
        if (tid < 64) {
            float s = 0.f;
            #pragma unroll
            for (int t = 0; t < 16; t++) s += red[tid * 17 + t];
            P[rowBase + tid] = (float)SEQ / (1.f + expf(-s));
        }
    }
}

// ---------------------------------------------------------------------------
// attn v3: chunked window (34 k's) + online softmax -> smem = ~35 KB
// -> 6 blocks/SM (occ 75%) instead of 2 (24%). Math stays fp32.
// ---------------------------------------------------------------------------
#define CHUNK   34
#define NCHUNK  3
// smem layout: win[CHUNK*CDIM] | sa[40] | sidx[104]
#define ATTN_SMEM_BYTES ((CHUNK * CDIM + 40) * 4 + 104 * 4)

__global__ void __launch_bounds__(256) attn_kernel(
    const float* __restrict__ q,     // [B, S, C]
    const float* __restrict__ u,     // [ROWS, C]
    const float* __restrict__ p,     // [ROWS]
    float* __restrict__ out)         // [ROWS, C]
{
    extern __shared__ float smem[];
    float* win  = smem;                        // [CHUNK][CDIM]
    float* sa   = win + CHUNK * CDIM;          // [40] chunk scores
    int*   sidx = (int*)(sa + 40);             // [104]

    const int r    = blockIdx.x;
    const int b    = r / SEQ;
    const int tid  = threadIdx.x;
    const int warp = tid >> 5;
    const int lane = tid & 31;

    const float pv = p[r];
    const float fp = truncf(pv);

    if (tid < KWIN) {
        int off   = tid - DHALF;
        float raw = truncf(pv + (float)off + 1.0f);
        int ri = (int)raw;
        ri = min(max(ri, 0), SEQ + 1);
        if (ri == SEQ + 1) ri = 0;             // % (S+1); 0 == invalid
        sidx[tid] = ri;
    }
    // per-lane u chunks in registers (c = 4*lane and 128 + 4*lane)
    const float4* uv = (const float4*)(u + (size_t)r * CDIM);
    const float4 u0 = uv[lane];
    const float4 u1 = uv[lane + 32];
    __syncthreads();

    const float4* qb = (const float4*)(q + (size_t)b * SEQ * CDIM);
    float4* winv = (float4*)win;

    float m_run   = -INFINITY;
    float Zrun    = 0.f;
    float out_acc = 0.f;

    #pragma unroll
    for (int chunk = 0; chunk < NCHUNK; chunk++) {
        const int c0 = chunk * CHUNK;

        // ---- phase 1: gather chunk L2->smem fused with score dot ----
        for (int j = warp; j < CHUNK; j += 8) {
            const int k  = c0 + j;
            const int ri = (k < KWIN) ? sidx[k] : 0;
            float4 a0 = make_float4(0.f, 0.f, 0.f, 0.f);
            float4 a1 = a0;
            if (ri != 0) {
                const float4* qr = qb + (size_t)(ri - 1) * (CDIM / 4);
                a0 = qr[lane];
                a1 = qr[lane + 32];
            }
            winv[j * (CDIM / 4) + lane]      = a0;
            winv[j * (CDIM / 4) + lane + 32] = a1;
            float s = a0.x * u0.x + a0.y * u0.y + a0.z * u0.z + a0.w * u0.w
                    + a1.x * u1.x + a1.y * u1.y + a1.z * u1.z + a1.w * u1.w;
            #pragma unroll
            for (int o = 16; o; o >>= 1)
                s += __shfl_xor_sync(0xffffffffu, s, o);
            if (lane == 0)
                sa[j] = (ri == 0) ? -INFINITY : s;
        }
        __syncthreads();

        // ---- phase 2: online softmax update (redundant per warp) ----
        // lane holds scores for j = lane and j = lane+32 (34 entries)
        float a_lo = sa[lane];
        float a_hi = (lane < CHUNK - 32) ? sa[lane + 32] : -INFINITY;
        float mc = fmaxf(a_lo, a_hi);
        #pragma unroll
        for (int o = 16; o; o >>= 1)
            mc = fmaxf(mc, __shfl_xor_sync(0xffffffffu, mc, o));
        float m_new = fmaxf(m_run, mc);

        float e_lo = 0.f, e_hi = 0.f, sc = 1.f;
        if (m_new != -INFINITY) {
            sc = __expf(m_run - m_new);        // exp(-inf)=0 on first update
            float ez_lo = __expf(a_lo - m_new);
            float ez_hi = __expf(a_hi - m_new);
            float zsum = ez_lo + ez_hi;
            #pragma unroll
            for (int o = 16; o; o >>= 1)
                zsum += __shfl_xor_sync(0xffffffffu, zsum, o);
            Zrun = Zrun * sc + zsum;
            // gaussian decay (numerator only; Z uses raw softmax weights)
            float d_lo = ((float)(c0 + lane - DHALF)      + fp - pv) / (float)DHALF;
            float d_hi = ((float)(c0 + lane + 32 - DHALF) + fp - pv) / (float)DHALF;
            e_lo = ez_lo * __expf(-2.f * d_lo * d_lo);
            e_hi = ez_hi * __expf(-2.f * d_hi * d_hi);
        }
        m_run = m_new;

        // ---- phase 3: accumulate output for this chunk ----
        out_acc *= sc;
        #pragma unroll
        for (int j = 0; j < CHUNK; j++) {
            float w = (j < 32) ? __shfl_sync(0xffffffffu, e_lo, j)
                               : __shfl_sync(0xffffffffu, e_hi, j - 32);
            out_acc += w * win[j * CDIM + tid];
        }
        __syncthreads();                       // win/sa consumed; next chunk may overwrite
    }

    out[(size_t)r * CDIM + tid] = out_acc / Zrun;
}

// ---------------------------------------------------------------------------
extern "C" void kernel_launch(void* const* d_in, const int* in_sizes, int n_in,
                              void* d_out, int out_size)
{
    const float* q   = (const float*)d_in[0];
    const float* c_t = (const float*)d_in[1];
    const float* W_a = (const float*)d_in[2];
    const float* W_p = (const float*)d_in[3];
    const float* V_p = (const float*)d_in[4];
    float* out = (float*)d_out;

    float* u = nullptr;
    float* p = nullptr;
    cudaGetSymbolAddress((void**)&u, g_u);
    cudaGetSymbolAddress((void**)&p, g_p);

    static_assert(ATTN_SMEM_BYTES < 48 * 1024, "smem budget");
    cudaFuncSetAttribute(attn_kernel, cudaFuncAttributeMaxDynamicSharedMemorySize,
                         ATTN_SMEM_BYTES);

    proj_kernel<<<192, 256>>>(c_t, W_a, W_p, V_p, u, p);
    attn_kernel<<<ROWS, 256, ATTN_SMEM_BYTES>>>(q, u, p, out);
}

// round 16
// speedup vs baseline: 1.7156x; 1.0158x over previous
#include <cuda_runtime.h>
#include <cuda_bf16.h>
#include <math.h>

// Problem constants (fixed by the reference setup)
#define BATCH 2
#define SEQ   2048
#define ROWS  (BATCH * SEQ)   // 4096
#define CDIM  256             // CQ == CC
#define DHALF 50
#define KWIN  101             // 2*D+1
#define PSIZE 100
#define JPAD  128             // PSIZE padded

// Scratch (allocation-free rule: __device__ globals)
__device__ float g_u[ROWS * CDIM];   // u = c_t @ W_a   [4096,256]
__device__ float g_p[ROWS];          // predicted centers

// ---------------------------------------------------------------------------
// Combined projection kernel, 192 blocks:
//   blocks [0,128):   u = c_t @ W_a   (128x64 tiles, BK=16, 8x4 microtile)
//   blocks [128,192): p = S*sigmoid(tanh(c_t@W_p^T)@V_p^T)   (64-row tiles)
// ---------------------------------------------------------------------------
#define PROJ_SBUF_FLOATS 7488   // max(u: 2240+1024, p: 2176+4224+1088)

__global__ void __launch_bounds__(256) proj_kernel(
    const float* __restrict__ A,     // c_t [4096,256]
    const float* __restrict__ W_a,   // [256,256]
    const float* __restrict__ W_p,   // [100,256]
    const float* __restrict__ V_p,   // [100]
    float* __restrict__ U,           // u [4096,256]
    float* __restrict__ P)           // p [4096]
{
    __shared__ __align__(16) float sbuf[PROJ_SBUF_FLOATS];

    const int tid = threadIdx.x;
    const int bid = blockIdx.x;

    if (bid < 128) {
        // ------- u GEMM: BM=128, BN=64, BK=16, 8x4 microtile -------
        float* As = sbuf;            // [16][140] transposed (k, m)
        float* Bs = sbuf + 2240;     // [16][64]
        const int rowBase = (bid >> 2) * 128;
        const int colBase = (bid & 3) * 64;
        const int tx = tid & 15;
        const int ty = tid >> 4;

        float acc[8][4] = {};

        for (int k0 = 0; k0 < CDIM; k0 += 16) {
            #pragma unroll
            for (int t = 0; t < 2; t++) {
                int i  = tid + t * 256;
                int r  = i >> 2;
                int c4 = i & 3;
                float4 v = *(const float4*)&A[(rowBase + r) * CDIM + k0 + c4 * 4];
                As[(c4 * 4 + 0) * 140 + r] = v.x;
                As[(c4 * 4 + 1) * 140 + r] = v.y;
                As[(c4 * 4 + 2) * 140 + r] = v.z;
                As[(c4 * 4 + 3) * 140 + r] = v.w;
            }
            {
                int r  = tid >> 4;
                int c4 = tid & 15;
                *(float4*)&Bs[r * 64 + c4 * 4] =
                    *(const float4*)&W_a[(k0 + r) * CDIM + colBase + c4 * 4];
            }
            __syncthreads();

            #pragma unroll
            for (int kk = 0; kk < 16; kk++) {
                float4 A0 = *(float4*)&As[kk * 140 + ty * 8];
                float4 A1 = *(float4*)&As[kk * 140 + ty * 8 + 4];
                float4 Bv = *(float4*)&Bs[kk * 64 + tx * 4];
                float am[8] = {A0.x, A0.y, A0.z, A0.w, A1.x, A1.y, A1.z, A1.w};
                #pragma unroll
                for (int i = 0; i < 8; i++) {
                    acc[i][0] += am[i] * Bv.x;
                    acc[i][1] += am[i] * Bv.y;
                    acc[i][2] += am[i] * Bv.z;
                    acc[i][3] += am[i] * Bv.w;
                }
            }
            __syncthreads();
        }

        #pragma unroll
        for (int i = 0; i < 8; i++) {
            float4 v = make_float4(acc[i][0], acc[i][1], acc[i][2], acc[i][3]);
            *(float4*)&U[(rowBase + ty * 8 + i) * CDIM + colBase + tx * 4] = v;
        }
    } else {
        // ------- p GEMM: 64 rows x 128(padded j) x 256 -------
        float* As  = sbuf;           // [32][68]
        float* Bs  = sbuf + 2176;    // [32][132]
        float* red = sbuf + 2176 + 4224;  // [64][17]
        const int rowBase = (bid - 128) * 64;
        const int tx = tid & 15;
        const int ty = tid >> 4;

        float vp[8];
        #pragma unroll
        for (int jj = 0; jj < 8; jj++) {
            int j = tx * 8 + jj;
            vp[jj] = (j < PSIZE) ? __ldg(V_p + j) : 0.f;
        }

        for (int i = tid; i < 32 * (JPAD - PSIZE); i += 256) {
            int k = i / (JPAD - PSIZE);
            int j = PSIZE + i % (JPAD - PSIZE);
            Bs[k * 132 + j] = 0.f;
        }

        float acc[4][8] = {};

        for (int k0 = 0; k0 < CDIM; k0 += 32) {
            #pragma unroll
            for (int t = 0; t < 2; t++) {
                int i  = tid + t * 256;
                int r  = i >> 3;
                int c4 = i & 7;
                float4 v = *(const float4*)&A[(rowBase + r) * CDIM + k0 + c4 * 4];
                As[(c4 * 4 + 0) * 68 + r] = v.x;
                As[(c4 * 4 + 1) * 68 + r] = v.y;
                As[(c4 * 4 + 2) * 68 + r] = v.z;
                As[(c4 * 4 + 3) * 68 + r] = v.w;
            }
            for (int i = tid; i < PSIZE * 8; i += 256) {
                int j  = i >> 3;
                int c4 = i & 7;
                float4 v = *(const float4*)&W_p[j * CDIM + k0 + c4 * 4];
                Bs[(c4 * 4 + 0) * 132 + j] = v.x;
                Bs[(c4 * 4 + 1) * 132 + j] = v.y;
                Bs[(c4 * 4 + 2) * 132 + j] = v.z;
                Bs[(c4 * 4 + 3) * 132 + j] = v.w;
            }
            __syncthreads();

            #pragma unroll
            for (int kk = 0; kk < 32; kk++) {
                float a0 = As[kk * 68 + ty * 4 + 0];
                float a1 = As[kk * 68 + ty * 4 + 1];
                float a2 = As[kk * 68 + ty * 4 + 2];
                float a3 = As[kk * 68 + ty * 4 + 3];
                float4 b0 = *(float4*)&Bs[kk * 132 + tx * 8 + 0];
                float4 b1 = *(float4*)&Bs[kk * 132 + tx * 8 + 4];
                acc[0][0] += a0 * b0.x; acc[0][1] += a0 * b0.y; acc[0][2] += a0 * b0.z; acc[0][3] += a0 * b0.w;
                acc[0][4] += a0 * b1.x; acc[0][5] += a0 * b1.y; acc[0][6] += a0 * b1.z; acc[0][7] += a0 * b1.w;
                acc[1][0] += a1 * b0.x; acc[1][1] += a1 * b0.y; acc[1][2] += a1 * b0.z; acc[1][3] += a1 * b0.w;
                acc[1][4] += a1 * b1.x; acc[1][5] += a1 * b1.y; acc[1][6] += a1 * b1.z; acc[1][7] += a1 * b1.w;
                acc[2][0] += a2 * b0.x; acc[2][1] += a2 * b0.y; acc[2][2] += a2 * b0.z; acc[2][3] += a2 * b0.w;
                acc[2][4] += a2 * b1.x; acc[2][5] += a2 * b1.y; acc[2][6] += a2 * b1.z; acc[2][7] += a2 * b1.w;
                acc[3][0] += a3 * b0.x; acc[3][1] += a3 * b0.y; acc[3][2] += a3 * b0.z; acc[3][3] += a3 * b0.w;
                acc[3][4] += a3 * b1.x; acc[3][5] += a3 * b1.y; acc[3][6] += a3 * b1.z; acc[3][7] += a3 * b1.w;
            }
            __syncthreads();
        }

        #pragma unroll
        for (int i = 0; i < 4; i++) {
            float s = 0.f;
            #pragma unroll
            for (int jj = 0; jj < 8; jj++)
                s += vp[jj] * tanhf(acc[i][jj]);
            red[(ty * 4 + i) * 17 + tx] = s;
        }
        __syncthreads();
        if (tid < 64) {
            float s = 0.f;
            #pragma unroll
            for (int t = 0; t < 16; t++) s += red[tid * 17 + t];
            P[rowBase + tid] = (float)SEQ / (1.f + expf(-s));
        }
    }
}

// ---------------------------------------------------------------------------
// attn v4: NO smem window. Score pass gathers q via LDG (fused dot); output
// pass RE-gathers the same rows via LDG (L1/L2-resident). smem = weights+idx
// only (~1 KB). Removes STS+LDS round-trip (~100 KB/block of L1 traffic) and
// the online-softmax machinery.
// ---------------------------------------------------------------------------
__global__ void __launch_bounds__(256, 6) attn_kernel(
    const float* __restrict__ q,     // [B, S, C]
    const float* __restrict__ u,     // [ROWS, C]
    const float* __restrict__ p,     // [ROWS]
    float* __restrict__ out)         // [ROWS, C]
{
    __shared__ float sa[104];        // scores -> final weights
    __shared__ int   sidx[104];

    const int r    = blockIdx.x;
    const int b    = r / SEQ;
    const int tid  = threadIdx.x;
    const int warp = tid >> 5;
    const int lane = tid & 31;

    const float pv = p[r];

    if (tid < KWIN) {
        int off   = tid - DHALF;
        float raw = truncf(pv + (float)off + 1.0f);
        int ri = (int)raw;
        ri = min(max(ri, 0), SEQ + 1);
        if (ri == SEQ + 1) ri = 0;             // % (S+1); 0 == invalid
        sidx[tid] = ri;
    }
    // per-lane u chunks in registers (c = 4*lane and 128 + 4*lane)
    const float4* uv = (const float4*)(u + (size_t)r * CDIM);
    const float4 u0 = uv[lane];
    const float4 u1 = uv[lane + 32];
    __syncthreads();

    const float* qb = q + (size_t)b * SEQ * CDIM;
    const float4* qb4 = (const float4*)qb;

    // ---- phase 1: scores a[k] = q1[k] . u  (warp per k, LDG fused dot) ----
    #pragma unroll 2
    for (int k = warp; k < KWIN; k += 8) {
        const int ri = sidx[k];
        float s = 0.f;
        if (ri != 0) {
            const float4* qr = qb4 + (size_t)(ri - 1) * (CDIM / 4);
            float4 a0 = qr[lane];
            float4 a1 = qr[lane + 32];
            s = a0.x * u0.x + a0.y * u0.y + a0.z * u0.z + a0.w * u0.w
              + a1.x * u1.x + a1.y * u1.y + a1.z * u1.z + a1.w * u1.w;
        }
        #pragma unroll
        for (int o = 16; o; o >>= 1)
            s += __shfl_xor_sync(0xffffffffu, s, o);
        if (lane == 0)
            sa[k] = (ri == 0) ? -INFINITY : s;
    }
    __syncthreads();

    // ---- phase 2: softmax + gaussian, fully normalized weights (warp 0) ----
    if (tid < 32) {
        float v[4];
        float m = -INFINITY;
        #pragma unroll
        for (int t = 0; t < 4; t++) {
            int k = tid + t * 32;
            v[t] = (k < KWIN) ? sa[k] : -INFINITY;
            m = fmaxf(m, v[t]);
        }
        #pragma unroll
        for (int o = 16; o; o >>= 1)
            m = fmaxf(m, __shfl_xor_sync(0xffffffffu, m, o));
        float ssum = 0.f;
        #pragma unroll
        for (int t = 0; t < 4; t++) {
            int k = tid + t * 32;
            float e = (k < KWIN) ? __expf(v[t] - m) : 0.f;
            v[t] = e;
            ssum += e;
        }
        #pragma unroll
        for (int o = 16; o; o >>= 1)
            ssum += __shfl_xor_sync(0xffffffffu, ssum, o);
        float inv = 1.f / ssum;
        float fp  = truncf(pv);
        #pragma unroll
        for (int t = 0; t < 4; t++) {
            int k = tid + t * 32;
            if (k < KWIN) {
                float d = ((float)(k - DHALF) + fp - pv) / (float)DHALF;
                sa[k] = v[t] * inv * __expf(-2.f * d * d);
            }
        }
    }
    __syncthreads();

    // ---- phase 3: out[c] = sum_k w[k] * q[row_k][c], re-gathered via LDG ----
    // Coalesced: thread tid reads element tid of each row (one 128B line per
    // warp per k, lines touched in phase 1). Independent loads -> deep MLP.
    float acc = 0.f;
    #pragma unroll 4
    for (int k = 0; k < KWIN; k++) {
        const int ri = sidx[k];
        if (ri != 0)
            acc += sa[k] * __ldg(qb + (size_t)(ri - 1) * CDIM + tid);
    }
    out[(size_t)r * CDIM + tid] = acc;
}

// ---------------------------------------------------------------------------
extern "C" void kernel_launch(void* const* d_in, const int* in_sizes, int n_in,
                              void* d_out, int out_size)
{
    const float* q   = (const float*)d_in[0];
    const float* c_t = (const float*)d_in[1];
    const float* W_a = (const float*)d_in[2];
    const float* W_p = (const float*)d_in[3];
    const float* V_p = (const float*)d_in[4];
    float* out = (float*)d_out;

    float* u = nullptr;
    float* p = nullptr;
    cudaGetSymbolAddress((void**)&u, g_u);
    cudaGetSymbolAddress((void**)&p, g_p);

    proj_kernel<<<192, 256>>>(c_t, W_a, W_p, V_p, u, p);
    attn_kernel<<<ROWS, 256>>>(q, u, p, out);
}